// round 9
// baseline (speedup 1.0000x reference)
#include <cuda_runtime.h>
#include <cuda_fp16.h>
#include <cstdint>

#define B_SZ    32
#define T_STEPS 200
#define E_DIM   32
#define H_DIM   128
#define V_DIM   8000
#define M_TOT   (B_SZ * T_STEPS)
#define OUT_SEQ_ELEMS ((size_t)M_TOT * V_DIM)

#define MBT 100                 // m-tiles of 64 rows (t-major: 2 timesteps x 32 batches)
#define NBT 63                  // n-tiles of 128
#define NT  (MBT * NBT)         // 6300
#define GRID_MAIN 148

// ---------------- globals ----------------------------------------------------
__device__ __align__(128) __half g_hs_h[M_TOT * H_DIM];    // t-major rows
__device__ __align__(128) __half g_vw_h[V_DIM * H_DIM];
__device__ __align__(128) __half g_vw_l[V_DIM * H_DIM];
__device__ __align__(128) float  g_ux[B_SZ * T_STEPS * H_DIM];
__device__ int g_cnt[128];      // per-m-tile completion count (==32 when ready)
__device__ int g_tile;          // work-stealing tile counter
__device__ int g_split;         // vw-split completion count (==116 when done)

__global__ void init_kernel() {
    int i = threadIdx.x;
    if (i < 128) g_cnt[i] = 0;
    if (i == 128) g_tile = 0;
    if (i == 129) g_split = 0;
}

// ---------------- packed f32x2 helpers ---------------------------------------
typedef unsigned long long ull;
__device__ __forceinline__ void fma2(ull& d, ull a, ull b) {
    asm("fma.rn.f32x2 %0, %1, %2, %0;" : "+l"(d) : "l"(a), "l"(b));
}
__device__ __forceinline__ ull pk(float x, float y) {
    ull r; asm("mov.b64 %0, {%1,%2};" : "=l"(r) : "f"(x), "f"(y)); return r;
}
__device__ __forceinline__ float2 upk(ull v) {
    float2 r; asm("mov.b64 {%0,%1}, %2;" : "=f"(r.x), "=f"(r.y) : "l"(v)); return r;
}

// ---------------- sync primitives --------------------------------------------
__device__ __forceinline__ int ld_acq(const int* p) {
    int v; asm volatile("ld.acquire.gpu.global.b32 %0, [%1];" : "=r"(v) : "l"(p));
    return v;
}
__device__ __forceinline__ void red_rel_add1(int* p) {
    asm volatile("red.release.gpu.global.add.s32 [%0], 1;" :: "l"(p) : "memory");
}

// ---------------- GEMM smem layout (worker role) -----------------------------
#define LDA2 136
#define SM_A   0                                   // 64 x 272B = 17408
#define TILE_AM (64 * LDA2 * 2)
#define TILE_BN (128 * LDA2 * 2)                   // 34816
#define SM_B(buf, half) (TILE_AM + ((buf) * 2 + (half)) * TILE_BN)
#define DYN_SMEM (TILE_AM + 4 * TILE_BN)           // 156672

#define MMA_FP16(C, A, Bf) asm volatile( \
    "mma.sync.aligned.m16n8k16.row.col.f32.f16.f16.f32 " \
    "{%0,%1,%2,%3}, {%4,%5,%6,%7}, {%8,%9}, {%0,%1,%2,%3};" \
    : "+f"((C)[0]), "+f"((C)[1]), "+f"((C)[2]), "+f"((C)[3]) \
    : "r"((A)[0]), "r"((A)[1]), "r"((A)[2]), "r"((A)[3]), \
      "r"((Bf)[0]), "r"((Bf)[1]))
#define LDSM4(R, P) asm volatile( \
    "ldmatrix.sync.aligned.m8n8.x4.shared.b16 {%0,%1,%2,%3}, [%4];" \
    : "=r"((R)[0]), "=r"((R)[1]), "=r"((R)[2]), "=r"((R)[3]) : "r"(P))
#define LDSM2(R, P) asm volatile( \
    "ldmatrix.sync.aligned.m8n8.x2.shared.b16 {%0,%1}, [%2];" \
    : "=r"((R)[0]), "=r"((R)[1]) : "r"(P))

__device__ __forceinline__ void cpa16(void* dst, const void* src, bool pred) {
    uint32_t d = (uint32_t)__cvta_generic_to_shared(dst);
    int sz = pred ? 16 : 0;
    asm volatile("cp.async.cg.shared.global [%0], [%1], 16, %2;"
                 :: "r"(d), "l"(src), "r"(sz) : "memory");
}
__device__ __forceinline__ void cpa_commit() {
    asm volatile("cp.async.commit_group;" ::: "memory");
}
__device__ __forceinline__ void cpa_wait_all() {
    asm volatile("cp.async.wait_group 0;" ::: "memory");
}

__device__ __forceinline__ void load_A(char* sm, int m, int tid) {
    char* As = sm + SM_A;
    #pragma unroll
    for (int it = 0; it < 4; it++) {
        int id  = it * 256 + tid;
        int row = id >> 4;
        int c   = (id & 15) * 8;
        cpa16(As + row * (LDA2 * 2) + c * 2,
              &g_hs_h[(size_t)(m * 64 + row) * H_DIM + c], true);
    }
}
__device__ __forceinline__ void load_B(char* sm, int buf, int nb, int tid) {
    char* Bh = sm + SM_B(buf, 0);
    char* Bl = sm + SM_B(buf, 1);
    #pragma unroll
    for (int it = 0; it < 8; it++) {
        int id  = it * 256 + tid;
        int row = id >> 4;
        int c   = (id & 15) * 8;
        int so  = row * (LDA2 * 2) + c * 2;
        bool ok = (nb * 128 + row) < V_DIM;
        const size_t g = (size_t)(nb * 128 + row) * H_DIM + c;
        cpa16(Bh + so, &g_vw_h[g], ok);
        cpa16(Bl + so, &g_vw_l[g], ok);
    }
}

// compute one 64x128 tile (2-pass fp16: Bh + Bl) and store with bias
__device__ __forceinline__ void compute_tile(char* sm, int buf, int m, int nb,
                                             const float* __restrict__ Vb,
                                             float* __restrict__ out, int tid) {
    const int w    = tid >> 5;
    const int lane = tid & 31;
    const int wm = (w >> 2) * 32;   // 0,32
    const int wn = (w & 3) * 32;    // 0,32,64,96
    const int a_rl = lane & 15;
    const int a_co = (lane >> 4) * 8;
    const int b_rl = lane & 7;
    const int b_co = lane & 8;
    char* Ahs = sm + SM_A;
    char* Bhs = sm + SM_B(buf, 0);
    char* Bls = sm + SM_B(buf, 1);

    float acc[2][4][4];
    #pragma unroll
    for (int i = 0; i < 2; i++)
        #pragma unroll
        for (int jj = 0; jj < 4; jj++)
            #pragma unroll
            for (int k = 0; k < 4; k++) acc[i][jj][k] = 0.0f;

    #pragma unroll
    for (int kc = 0; kc < 8; kc++) {
        const int kb = kc * 16;
        unsigned ah[2][4], bh[4][2], bl[4][2];
        #pragma unroll
        for (int rb = 0; rb < 2; rb++) {
            unsigned p = (unsigned)__cvta_generic_to_shared(
                Ahs + (wm + rb * 16 + a_rl) * (LDA2 * 2) + (kb + a_co) * 2);
            LDSM4(ah[rb], p);
        }
        #pragma unroll
        for (int cb = 0; cb < 4; cb++) {
            unsigned p = (unsigned)__cvta_generic_to_shared(
                Bhs + (wn + cb * 8 + b_rl) * (LDA2 * 2) + (kb + b_co) * 2);
            LDSM2(bh[cb], p);
            p = (unsigned)__cvta_generic_to_shared(
                Bls + (wn + cb * 8 + b_rl) * (LDA2 * 2) + (kb + b_co) * 2);
            LDSM2(bl[cb], p);
        }
        #pragma unroll
        for (int rb = 0; rb < 2; rb++)
            #pragma unroll
            for (int cb = 0; cb < 4; cb++)
                MMA_FP16(acc[rb][cb], ah[rb], bh[cb]);
        #pragma unroll
        for (int rb = 0; rb < 2; rb++)
            #pragma unroll
            for (int cb = 0; cb < 4; cb++)
                MMA_FP16(acc[rb][cb], ah[rb], bl[cb]);
    }

    // epilogue: rows are t-major (r = t*32 + b) -> out row = b*200 + t
    #pragma unroll
    for (int rb = 0; rb < 2; rb++) {
        int r0 = m * 64 + wm + rb * 16 + (lane >> 2);
        int or0 = (r0 & 31) * T_STEPS + (r0 >> 5);
        int r1 = r0 + 8;
        int or1 = (r1 & 31) * T_STEPS + (r1 >> 5);
        #pragma unroll
        for (int cb = 0; cb < 4; cb++) {
            int col = nb * 128 + wn + cb * 8 + (lane & 3) * 2;
            if (col < V_DIM) {
                float2 bv = *(const float2*)&Vb[col];
                float2 o0, o1;
                o0.x = acc[rb][cb][0] + bv.x; o0.y = acc[rb][cb][1] + bv.y;
                o1.x = acc[rb][cb][2] + bv.x; o1.y = acc[rb][cb][3] + bv.y;
                *(float2*)&out[(size_t)or0 * V_DIM + col] = o0;
                *(float2*)&out[(size_t)or1 * V_DIM + col] = o1;
            }
        }
    }
}

// ---------------- fused persistent kernel ------------------------------------
__global__ void __launch_bounds__(256) fused_kernel(
    const float* __restrict__ x,  const float* __restrict__ Ww,
    const float* __restrict__ Wb, const float* __restrict__ Uw,
    const float* __restrict__ Ub, const float* __restrict__ Vw,
    const float* __restrict__ Vb, float* __restrict__ out,
    float* __restrict__ hidden_out)
{
    extern __shared__ __align__(16) char dynsm[];
    __shared__ int s_tau[2];
    const int tid = threadIdx.x;
    const int cta = blockIdx.x;

    if (cta < B_SZ) {
        // ================= RECURRENCE (producer) =================
        float* xs = (float*)dynsm;                  // 200*32 floats
        float* hb = xs + T_STEPS * E_DIM;           // 2*136 floats
        const int b = cta;

        const float* xb = x + (size_t)b * T_STEPS * E_DIM;
        for (int i = tid; i < T_STEPS * E_DIM; i += 256) xs[i] = xb[i];
        if (tid < 136) { hb[tid] = 0.0f; hb[136 + tid] = 0.0f; }
        __syncthreads();

        // phase 1: ux -> global scratch
        {
            const int jj = tid & 127;
            const int g  = tid >> 7;
            ull up[16];
            const float2* ur = (const float2*)(Uw + jj * E_DIM);
            #pragma unroll
            for (int i = 0; i < 16; i++) { float2 v = ur[i]; up[i] = pk(v.x, v.y); }
            const float biasj = Wb[jj] + Ub[jj];
            float* uxb = g_ux + (size_t)b * T_STEPS * H_DIM;
            for (int t = g * 100; t < g * 100 + 100; t++) {
                ull a[4];
                a[0] = pk(0.f, 0.f); a[1] = a[0]; a[2] = a[0]; a[3] = a[0];
                const ulonglong2* xt = (const ulonglong2*)(xs + t * E_DIM);
                #pragma unroll
                for (int i = 0; i < 8; i++) {
                    ulonglong2 v = xt[i];
                    fma2(a[(2 * i) & 3],     up[2 * i],     v.x);
                    fma2(a[(2 * i + 1) & 3], up[2 * i + 1], v.y);
                }
                float2 s0 = upk(a[0]), s1 = upk(a[1]), s2 = upk(a[2]), s3 = upk(a[3]);
                uxb[t * H_DIM + jj] = ((s0.x + s0.y) + (s1.x + s1.y))
                                    + ((s2.x + s2.y) + (s3.x + s3.y)) + biasj;
            }
        }

        // phase 2: recurrence; tid = j*2 + q
        const int j = tid >> 1;
        const int q = tid & 1;
        ull wp[32];
        {
            const float4* wr = (const float4*)(Ww + j * H_DIM + q * 64);
            #pragma unroll
            for (int i = 0; i < 16; i++) {
                float4 v = wr[i];
                wp[2 * i]     = pk(v.x, v.y);
                wp[2 * i + 1] = pk(v.z, v.w);
            }
        }
        __syncthreads();

        const int hrd = q * 68;
        const int wch = (j >> 6) * 68 + (j & 63);
        const float* uxb = g_ux + (size_t)b * T_STEPS * H_DIM;
        float ucur = (q == 0) ? uxb[j] : 0.0f;

        for (int t = 0; t < T_STEPS; t++) {
            float unext = 0.0f;
            if (q == 0 && t + 1 < T_STEPS) unext = uxb[(t + 1) * H_DIM + j];

            const ulonglong2* hr = (const ulonglong2*)(hb + (t & 1) * 136 + hrd);
            ull a[4];
            a[0] = pk(0.f, 0.f); a[1] = a[0]; a[2] = a[0]; a[3] = a[0];
            #pragma unroll
            for (int i = 0; i < 16; i++) {
                ulonglong2 v = hr[i];
                fma2(a[(2 * i) & 3],     wp[2 * i],     v.x);
                fma2(a[(2 * i + 1) & 3], wp[2 * i + 1], v.y);
            }
            float2 s0 = upk(a[0]), s1 = upk(a[1]), s2 = upk(a[2]), s3 = upk(a[3]);
            float acc = ((s0.x + s0.y) + (s1.x + s1.y))
                      + ((s2.x + s2.y) + (s3.x + s3.y));
            acc += __shfl_xor_sync(0xffffffffu, acc, 1);

            if (q == 0) {
                acc += ucur;
                float e;
                asm("ex2.approx.f32 %0, %1;" : "=f"(e)
                    : "f"(acc * 2.8853900817779268f));
                float r;
                asm("rcp.approx.f32 %0, %1;" : "=f"(r) : "f"(e + 1.0f));
                float hv = fmaf(-2.0f, r, 1.0f);
                hb[((t + 1) & 1) * 136 + wch] = hv;
                g_hs_h[((size_t)t * B_SZ + b) * H_DIM + j] = __float2half(hv);
                if (t == T_STEPS - 1) hidden_out[b * H_DIM + j] = hv;
            }
            ucur = unext;
            if (t & 1) __threadfence();
            __syncthreads();
            if ((t & 1) && tid == 0) red_rel_add1(&g_cnt[t >> 1]);
        }
    } else {
        // ================= Vw split (116 CTAs) =================
        const int nblk = GRID_MAIN - B_SZ;
        for (int i = (cta - B_SZ) * 256 + tid; i < V_DIM * H_DIM;
             i += nblk * 256) {
            float v = Vw[i];
            __half h = __float2half(v);
            g_vw_h[i] = h;
            g_vw_l[i] = __float2half(v - __half2float(h));
        }
        __threadfence();
        __syncthreads();
        if (tid == 0) red_rel_add1(&g_split);
    }

    // ================= GEMM worker pool (all CTAs) =================
    if (tid == 0) {
        while (ld_acq(&g_split) < GRID_MAIN - B_SZ) __nanosleep(128);
        s_tau[0] = atomicAdd(&g_tile, 1);
    }
    __syncthreads();

    int tau = s_tau[0];
    int mres = -1;
    int buf = 0;
    bool havePref = false;

    while (tau < NT) {
        const int m  = tau / NBT;
        const int nb = tau % NBT;

        if (!havePref) {
            if (tid == 0) {
                while (ld_acq(&g_cnt[m]) < B_SZ) __nanosleep(128);
            }
            __syncthreads();
            if (m != mres) { load_A(dynsm, m, tid); mres = m; }
            load_B(dynsm, buf, nb, tid);
            cpa_commit();
            cpa_wait_all();
            __syncthreads();
        } else if (m != mres) {       // prefetched B but new A (can't happen: pref only same m)
            mres = m;
        }

        // lookahead grab + B prefetch into alternate buffer
        if (tid == 0) s_tau[buf ^ 1] = atomicAdd(&g_tile, 1);
        __syncthreads();
        int tau2 = s_tau[buf ^ 1];
        bool pref2 = (tau2 < NT) && (tau2 / NBT == m);
        if (pref2) { load_B(dynsm, buf ^ 1, tau2 % NBT, tid); cpa_commit(); }

        compute_tile(dynsm, buf, m, nb, Vb, out, tid);
        __syncthreads();              // all frag reads done
        if (pref2) cpa_wait_all();    // prefetch landed during compute

        tau = tau2;
        havePref = pref2;
        buf ^= 1;
    }
}

// ---------------- launch ----------------------------------------------------
extern "C" void kernel_launch(void* const* d_in, const int* in_sizes, int n_in,
                              void* d_out, int out_size) {
    const float* x  = (const float*)d_in[0];
    const float* Ww = (const float*)d_in[1];
    const float* Wb = (const float*)d_in[2];
    const float* Uw = (const float*)d_in[3];
    const float* Ub = (const float*)d_in[4];
    const float* Vw = (const float*)d_in[5];
    const float* Vb = (const float*)d_in[6];
    float* out = (float*)d_out;

    cudaFuncSetAttribute(fused_kernel,
                         cudaFuncAttributeMaxDynamicSharedMemorySize, DYN_SMEM);

    init_kernel<<<1, 256>>>();
    fused_kernel<<<GRID_MAIN, 256, DYN_SMEM>>>(x, Ww, Wb, Uw, Ub, Vw, Vb, out,
                                               out + OUT_SEQ_ELEMS);
}